// round 3
// baseline (speedup 1.0000x reference)
#include <cuda_runtime.h>
#include <cstdint>

// ---------------- problem constants ----------------
#define BB   64
#define TT   512
#define BT   (BB*TT)          // 32768
#define SKD  256
#define AND_ 96
#define DD   352              // SK+AN
#define HH   256
#define G4   1024             // 4*H
#define ATTD 80
#define NC   2000
#define RES_ELEMS ((size_t)BT*NC)    // 65,536,000
#define SAE_ELEMS ((size_t)BT*DD)    // 11,534,336

// ---------------- device scratch (static, allowed) ----------------
__device__ float g_sae  [BT*DD];          // 46 MB
__device__ float g_xg   [BT*G4];          // 134 MB
__device__ float g_hall [BT*HH];          // 33.5 MB
__device__ float g_P    [BT*ATTD];        // 10.5 MB
__device__ float g_scores[BT];
__device__ float g_final[BT*2*HH];        // 67 MB
__device__ float g_hbuf [2][BB][HH];      // ping-pong h state
__device__ int   g_cnt  [8];              // per batch-group barrier counters

// ---------------- helpers ----------------
__device__ __forceinline__ uint32_t f2tf(float f){
    uint32_t u; asm("cvt.rna.tf32.f32 %0, %1;" : "=r"(u) : "f"(f)); return u;
}
__device__ __forceinline__ float sigf(float x){ return 1.f/(1.f+__expf(-x)); }

// ---------------- reset: counters + h0 = 0 ----------------
__global__ void atkt_reset_kernel(){
    int idx = blockIdx.x*blockDim.x + threadIdx.x;
    if (idx < 2*BB*HH) ((float*)g_hbuf)[idx] = 0.f;
    if (idx < 8) g_cnt[idx] = 0;
}

// ---------------- embedding gather + concat (+optional out tail) ----------------
__global__ void atkt_embed_kernel(const int* __restrict__ skill,
                                  const int* __restrict__ answer,
                                  const float* __restrict__ skill_emb,
                                  const float* __restrict__ answer_emb,
                                  float* __restrict__ out_sae /*nullable*/){
    int bt = blockIdx.x;
    int d  = threadIdx.x;            // 0..351
    int ans = answer[bt];
    int sk  = skill[bt];
    float v;
    if (ans == 1) v = (d < SKD) ? skill_emb[sk*SKD + d]
                                : answer_emb[ans*AND_ + (d - SKD)];
    else          v = (d < AND_) ? answer_emb[ans*AND_ + d]
                                 : skill_emb[sk*SKD + (d - AND_)];
    size_t idx = (size_t)bt*DD + d;
    g_sae[idx] = v;
    if (out_sae) out_sae[idx] = v;
}

// ---------------- generic tf32 mma GEMM: C = act(A(MxK) * B(NxK)^T + bias) ----
// block tile 128x128, K-tile 32, 8 warps (2M x 4N), warp tile 64x32.
// requires: M % 128 == 0, K % 32 == 0.  act: 0=none, 1=sigmoid, 2=tanh
__global__ __launch_bounds__(256)
void atkt_gemm_tf32(const float* __restrict__ A, const float* __restrict__ Bm,
                    const float* __restrict__ bias1, const float* __restrict__ bias2,
                    float* __restrict__ C, int M, int N, int K, int act){
    __shared__ uint32_t As[128*36];
    __shared__ uint32_t Bs[128*36];
    const int tid  = threadIdx.x;
    const int lane = tid & 31, warp = tid >> 5;
    const int bm = blockIdx.y * 128, bn = blockIdx.x * 128;
    const int wm = (warp & 1) * 64, wn = (warp >> 1) * 32;

    float acc[4][4][4];
    #pragma unroll
    for (int i=0;i<4;i++)
      #pragma unroll
      for (int j=0;j<4;j++)
        #pragma unroll
        for (int q=0;q<4;q++) acc[i][j][q]=0.f;

    const int r0 = tid >> 3;         // 0..31
    const int c0 = (tid & 7) * 4;    // 0..28

    for (int kb = 0; kb < K; kb += 32){
        __syncthreads();
        #pragma unroll
        for (int i=0;i<4;i++){
            int row = r0 + 32*i;
            float4 va = *(const float4*)(A + (size_t)(bm+row)*K + kb + c0);
            *(uint4*)&As[row*36 + c0] =
                make_uint4(f2tf(va.x), f2tf(va.y), f2tf(va.z), f2tf(va.w));
            int gn = bn + row;
            float4 vb = make_float4(0.f,0.f,0.f,0.f);
            if (gn < N) vb = *(const float4*)(Bm + (size_t)gn*K + kb + c0);
            *(uint4*)&Bs[row*36 + c0] =
                make_uint4(f2tf(vb.x), f2tf(vb.y), f2tf(vb.z), f2tf(vb.w));
        }
        __syncthreads();
        #pragma unroll
        for (int kk = 0; kk < 32; kk += 8){
            uint32_t af[4][4], bf[4][2];
            #pragma unroll
            for (int ma=0; ma<4; ma++){
                int row = wm + ma*16 + (lane>>2);
                int col = kk + (lane&3);
                af[ma][0] = As[row*36 + col];
                af[ma][1] = As[(row+8)*36 + col];
                af[ma][2] = As[row*36 + col + 4];
                af[ma][3] = As[(row+8)*36 + col + 4];
            }
            #pragma unroll
            for (int na=0; na<4; na++){
                int row = wn + na*8 + (lane>>2);
                int col = kk + (lane&3);
                bf[na][0] = Bs[row*36 + col];
                bf[na][1] = Bs[row*36 + col + 4];
            }
            #pragma unroll
            for (int ma=0; ma<4; ma++)
                #pragma unroll
                for (int na=0; na<4; na++){
                    asm volatile(
                      "mma.sync.aligned.m16n8k8.row.col.f32.tf32.tf32.f32 "
                      "{%0,%1,%2,%3}, {%4,%5,%6,%7}, {%8,%9}, {%0,%1,%2,%3};\n"
                      : "+f"(acc[ma][na][0]), "+f"(acc[ma][na][1]),
                        "+f"(acc[ma][na][2]), "+f"(acc[ma][na][3])
                      : "r"(af[ma][0]), "r"(af[ma][1]), "r"(af[ma][2]), "r"(af[ma][3]),
                        "r"(bf[na][0]), "r"(bf[na][1]));
                }
        }
    }
    // epilogue: c0->(r,c) c1->(r,c+1) c2->(r+8,c) c3->(r+8,c+1)
    #pragma unroll
    for (int ma=0; ma<4; ma++){
        int row = bm + wm + ma*16 + (lane>>2);
        #pragma unroll
        for (int na=0; na<4; na++){
            int col = bn + wn + na*8 + (lane&3)*2;
            #pragma unroll
            for (int q=0;q<4;q++){
                int rr = row + ((q>=2) ? 8 : 0);
                int cc = col + (q&1);
                if (cc < N){
                    float x = acc[ma][na][q] + bias1[cc];
                    if (bias2) x += bias2[cc];
                    if (act==1)      x = 1.f/(1.f+__expf(-x));
                    else if (act==2) x = tanhf(x);
                    C[(size_t)rr*N + cc] = x;
                }
            }
        }
    }
}

// ---------------- persistent LSTM scan ----------------
// 128 blocks = 8 batch-groups x 16 h-slices, 128 threads each.
// Block caches its 64x256 Whh slice in smem; per-group 16-block barrier per step.
extern __shared__ float lstm_smem[];
__global__ __launch_bounds__(128)
void atkt_lstm_kernel(const float* __restrict__ Whh){
    float* Wsh = lstm_smem;                 // [4][16][256] = 64KB
    float* hsh = lstm_smem + 4*16*256;      // [8][256]    = 8KB
    const int tid = threadIdx.x;
    const int bg  = blockIdx.x >> 4;        // 0..7  batch group
    const int hs  = blockIdx.x & 15;        // 0..15 h slice
    const int bl  = tid & 7;                // local batch
    const int jl  = tid >> 3;               // local h dim 0..15
    const int b   = bg*8 + bl;
    const int j   = hs*16 + jl;

    // load Whh slice: rows {j, 256+j, 512+j, 768+j} for the 16 owned j's
    for (int idx = tid; idx < 4*16*256; idx += 128){
        int gate = idx >> 12;
        int jj   = (idx >> 8) & 15;
        int k    = idx & 255;
        Wsh[idx] = Whh[((gate<<8) + (hs<<4) + jj)*256 + k];
    }
    float c = 0.f;
    for (int t = 0; t < TT; ++t){
        __syncthreads();   // also gates on tid0's barrier spin from previous step
        // stage h_{t-1} for our 8 batches (ping-pong buffer, L2-coherent reads)
        {
            const float4* hsrc = (const float4*)&g_hbuf[t & 1][bg*8][0]; // 512 f4
            #pragma unroll
            for (int i = 0; i < 4; ++i){
                int idx = tid + i*128;
                ((float4*)hsh)[idx] = __ldcg(hsrc + idx);
            }
        }
        __syncthreads();
        const int bt = b*TT + t;
        const float* xr = g_xg + (size_t)bt*G4;
        float ai = xr[j], af = xr[256+j], ag = xr[512+j], ao = xr[768+j];
        const float4* hv = (const float4*)&hsh[bl*256];
        const float4* wi = (const float4*)&Wsh[(0*16 + jl)*256];
        const float4* wf = (const float4*)&Wsh[(1*16 + jl)*256];
        const float4* wg = (const float4*)&Wsh[(2*16 + jl)*256];
        const float4* wo = (const float4*)&Wsh[(3*16 + jl)*256];
        #pragma unroll 8
        for (int k4 = 0; k4 < 64; ++k4){
            float4 h4 = hv[k4];
            float4 w;
            w = wi[k4]; ai += h4.x*w.x; ai += h4.y*w.y; ai += h4.z*w.z; ai += h4.w*w.w;
            w = wf[k4]; af += h4.x*w.x; af += h4.y*w.y; af += h4.z*w.z; af += h4.w*w.w;
            w = wg[k4]; ag += h4.x*w.x; ag += h4.y*w.y; ag += h4.z*w.z; ag += h4.w*w.w;
            w = wo[k4]; ao += h4.x*w.x; ao += h4.y*w.y; ao += h4.z*w.z; ao += h4.w*w.w;
        }
        c = sigf(af)*c + sigf(ai)*tanhf(ag);
        float h = sigf(ao)*tanhf(c);
        g_hall[(size_t)bt*HH + j] = h;
        __stcg(&g_hbuf[(t+1)&1][b][j], h);
        __threadfence();       // release our h store to GPU scope
        __syncthreads();       // all threads of block released before arrive
        if (tid == 0){
            atomicAdd(&g_cnt[bg], 1);
            int tgt = 16*(t+1);
            int v;
            do {
                asm volatile("ld.global.acquire.gpu.s32 %0, [%1];"
                             : "=r"(v) : "l"(&g_cnt[bg]) : "memory");
            } while (v < tgt);
        }
    }
}

// ---------------- scores = P(32768x80) . sim_w ----------------
__global__ void atkt_score_reduce(const float* __restrict__ sim_w){
    int r = blockIdx.x*8 + (threadIdx.x >> 5);
    int lane = threadIdx.x & 31;
    float p = 0.f;
    for (int a = lane; a < ATTD; a += 32)
        p += g_P[(size_t)r*ATTD + a] * sim_w[a];
    #pragma unroll
    for (int o = 16; o; o >>= 1) p += __shfl_xor_sync(0xffffffffu, p, o);
    if (lane == 0) g_scores[r] = p;
}

// ---------------- causal attention + exclusive cumsum; builds final=[cum1|h] --
__global__ void atkt_attn_kernel(){
    const int b = blockIdx.x;
    const int tid = threadIdx.x;           // 256 = H
    __shared__ float e_sh[TT];
    __shared__ float red[256];
    float m = -1e30f;
    for (int t = tid; t < TT; t += 256) m = fmaxf(m, g_scores[b*TT + t]);
    red[tid] = m; __syncthreads();
    for (int s = 128; s; s >>= 1){
        if (tid < s) red[tid] = fmaxf(red[tid], red[tid+s]);
        __syncthreads();
    }
    float mm = red[0];
    for (int t = tid; t < TT; t += 256) e_sh[t] = __expf(g_scores[b*TT + t] - mm);
    __syncthreads();
    const int j = tid;
    float num = 0.f, den = 0.f, acc2 = 0.f;
    for (int t = 0; t < TT; ++t){
        float hv = g_hall[((size_t)b*TT + t)*HH + j];
        float ev = e_sh[t];
        den += ev; num += ev*hv;
        float attn = num/den;
        size_t o = ((size_t)b*TT + t)*(2*HH);
        g_final[o + j]      = acc2;        // exclusive cumsum of attn
        g_final[o + HH + j] = hv;
        acc2 += attn;
    }
}

// ---------------- host launch ----------------
extern "C" void kernel_launch(void* const* d_in, const int* in_sizes, int n_in,
                              void* d_out, int out_size){
    const int*   skill      = (const int*)  d_in[0];
    const int*   answer     = (const int*)  d_in[1];
    const float* skill_emb  = (const float*)d_in[2];
    const float* answer_emb = (const float*)d_in[3];
    const float* Wih        = (const float*)d_in[4];
    const float* Whh        = (const float*)d_in[5];
    const float* bih        = (const float*)d_in[6];
    const float* bhh        = (const float*)d_in[7];
    const float* mlp_w      = (const float*)d_in[8];
    const float* mlp_b      = (const float*)d_in[9];
    const float* sim_w      = (const float*)d_in[10];
    const float* fc_w       = (const float*)d_in[11];
    const float* fc_b       = (const float*)d_in[12];
    float* out = (float*)d_out;

    float *p_sae, *p_xg, *p_hall, *p_P, *p_final;
    cudaGetSymbolAddress((void**)&p_sae,   g_sae);
    cudaGetSymbolAddress((void**)&p_xg,    g_xg);
    cudaGetSymbolAddress((void**)&p_hall,  g_hall);
    cudaGetSymbolAddress((void**)&p_P,     g_P);
    cudaGetSymbolAddress((void**)&p_final, g_final);

    cudaFuncSetAttribute(atkt_lstm_kernel,
                         cudaFuncAttributeMaxDynamicSharedMemorySize, 73728);

    float* out_sae = ((size_t)out_size >= RES_ELEMS + SAE_ELEMS)
                     ? (out + RES_ELEMS) : nullptr;

    // 1) reset barrier counters + h0
    atkt_reset_kernel<<<(2*BB*HH + 1023)/1024, 1024>>>();
    // 2) embeddings -> sae (+ tail of output)
    atkt_embed_kernel<<<BT, DD>>>(skill, answer, skill_emb, answer_emb, out_sae);
    // 3) xg = sae @ Wih^T + bih + bhh   [32768 x 1024]
    atkt_gemm_tf32<<<dim3(G4/128, BT/128), 256>>>(
        p_sae, Wih, bih, bhh, p_xg, BT, G4, DD, 0);
    // 4) LSTM scan -> g_hall
    atkt_lstm_kernel<<<128, 128, 73728>>>(Whh);
    // 5) P = tanh(h @ mlp_w^T + mlp_b)  [32768 x 80]
    atkt_gemm_tf32<<<dim3(1, BT/128), 256>>>(
        p_hall, mlp_w, mlp_b, nullptr, p_P, BT, ATTD, HH, 2);
    // 6) scores = P . sim_w
    atkt_score_reduce<<<BT/8, 256>>>(sim_w);
    // 7) causal attention cumulative ratios -> final = [cum1 | h]
    atkt_attn_kernel<<<BB, HH>>>();
    // 8) res = sigmoid(final @ fc_w^T + fc_b)  [32768 x 2000] -> d_out
    atkt_gemm_tf32<<<dim3((NC + 127)/128, BT/128), 256>>>(
        p_final, fc_w, fc_b, nullptr, out, BT, NC, 2*HH, 1);
}

// round 4
// speedup vs baseline: 1.0298x; 1.0298x over previous
#include <cuda_runtime.h>
#include <cstdint>

// ---------------- problem constants ----------------
#define BB   64
#define TT   512
#define BT   (BB*TT)          // 32768
#define SKD  256
#define AND_ 96
#define DD   352              // SK+AN
#define HH   256
#define G4   1024             // 4*H
#define ATTD 80
#define NC   2000
#define RES_ELEMS ((size_t)BT*NC)    // 65,536,000
#define SAE_ELEMS ((size_t)BT*DD)    // 11,534,336

typedef unsigned long long u64;

// ---------------- device scratch (static, allowed) ----------------
__device__ float g_sae  [BT*DD];          // 46 MB (pre-rounded tf32)
__device__ float g_xg   [BT*G4];          // 134 MB
__device__ float g_hall [BT*HH];          // 33.5 MB (pre-rounded tf32)
__device__ float g_P    [BT*ATTD];        // 10.5 MB
__device__ float g_scores[BT];
__device__ float g_final[BT*2*HH];        // 67 MB (pre-rounded tf32)
__device__ float g_hbuf [2][BB][HH];      // ping-pong h state (full fp32)
__device__ int   g_cnt  [8];              // per batch-group barrier counters
// pre-rounded weight copies
__device__ float g_wih_r [G4*DD];         // 1.4 MB
__device__ float g_mlpw_r[ATTD*HH];
__device__ float g_fcw_r [NC*2*HH];       // 4.1 MB

extern __shared__ float dynsmem[];

// ---------------- helpers ----------------
__device__ __forceinline__ uint32_t f2tf(float f){
    uint32_t u; asm("cvt.rna.tf32.f32 %0, %1;" : "=r"(u) : "f"(f)); return u;
}
__device__ __forceinline__ float rnd_tf(float f){ return __uint_as_float(f2tf(f)); }
__device__ __forceinline__ float sigf(float x){ return 1.f/(1.f+__expf(-x)); }
__device__ __forceinline__ void ffma2(u64& d, u64 a, u64 b){
    asm volatile("fma.rn.f32x2 %0, %1, %2, %0;" : "+l"(d) : "l"(a), "l"(b));
}
__device__ __forceinline__ u64 pack1(float x){
    float2 f = make_float2(x, 0.f); return *reinterpret_cast<u64*>(&f);
}
__device__ __forceinline__ float hsum2(u64 v){
    float2 f = *reinterpret_cast<float2*>(&v); return f.x + f.y;
}
__device__ __forceinline__ void cpa16(uint32_t s, const void* g){
    asm volatile("cp.async.cg.shared.global [%0], [%1], 16;\n" :: "r"(s), "l"(g));
}
__device__ __forceinline__ void cpa16z(uint32_t s, const void* g, int ok){
    int bytes = ok ? 16 : 0;
    asm volatile("cp.async.cg.shared.global [%0], [%1], 16, %2;\n"
                 :: "r"(s), "l"(g), "r"(bytes));
}

// ---------------- tf32 pre-round kernel ----------------
__global__ void atkt_round_tf32(const float* __restrict__ src,
                                float* __restrict__ dst, int n){
    int i = blockIdx.x*blockDim.x + threadIdx.x;
    if (i < n) dst[i] = rnd_tf(src[i]);
}

// ---------------- reset: counters + h0 = 0 ----------------
__global__ void atkt_reset_kernel(){
    int idx = blockIdx.x*blockDim.x + threadIdx.x;
    if (idx < 2*BB*HH) ((float*)g_hbuf)[idx] = 0.f;
    if (idx < 8) g_cnt[idx] = 0;
}

// ---------------- embedding gather + concat ----------------
__global__ void atkt_embed_kernel(const int* __restrict__ skill,
                                  const int* __restrict__ answer,
                                  const float* __restrict__ skill_emb,
                                  const float* __restrict__ answer_emb,
                                  float* __restrict__ out_sae /*nullable*/){
    int bt = blockIdx.x;
    int d  = threadIdx.x;            // 0..351
    int ans = answer[bt];
    int sk  = skill[bt];
    float v;
    if (ans == 1) v = (d < SKD) ? skill_emb[sk*SKD + d]
                                : answer_emb[ans*AND_ + (d - SKD)];
    else          v = (d < AND_) ? answer_emb[ans*AND_ + d]
                                 : skill_emb[sk*SKD + (d - AND_)];
    size_t idx = (size_t)bt*DD + d;
    g_sae[idx] = rnd_tf(v);          // GEMM operand: pre-rounded
    if (out_sae) out_sae[idx] = v;   // exact output
}

// ---------------- pipelined tf32 mma GEMM ----------------
// C(MxN) = act(A(MxK) * B(NxK)^T + bias),  operands pre-rounded to tf32.
// block tile 128x128, K-tile 32, 2-stage cp.async double buffer, 8 warps.
// M%128==0, K%32==0.  act: 0=none, 1=sigmoid, 2=tanh
#define GSZ (128*36)
__global__ __launch_bounds__(256, 2)
void atkt_gemm_tf32(const float* __restrict__ A, const float* __restrict__ Bm,
                    const float* __restrict__ bias1, const float* __restrict__ bias2,
                    float* __restrict__ C, int M, int N, int K, int act){
    float* As = dynsmem;            // [2][128*36]
    float* Bs = dynsmem + 2*GSZ;    // [2][128*36]
    const int tid  = threadIdx.x;
    const int lane = tid & 31, warp = tid >> 5;
    const int bm = blockIdx.y * 128, bn = blockIdx.x * 128;
    const int wm = (warp & 1) * 64, wn = (warp >> 1) * 32;

    float acc[4][4][4];
    #pragma unroll
    for (int i=0;i<4;i++)
      #pragma unroll
      for (int j=0;j<4;j++)
        #pragma unroll
        for (int q=0;q<4;q++) acc[i][j][q]=0.f;

    const int nkt = K >> 5;

    // stage loader: 1024 16B chunks per array, 4 per thread per array
    auto load_stage = [&](int s, int kb){
        #pragma unroll
        for (int i = 0; i < 4; ++i){
            int idx = tid + i*256;
            int row = idx >> 3;
            int col = (idx & 7) * 4;
            uint32_t sa = (uint32_t)__cvta_generic_to_shared(
                              &As[s*GSZ + row*36 + col]);
            cpa16(sa, A + (size_t)(bm + row)*K + kb + col);
            int gn = bn + row;
            int gnc = (gn < N) ? gn : (N - 1);
            uint32_t sb = (uint32_t)__cvta_generic_to_shared(
                              &Bs[s*GSZ + row*36 + col]);
            cpa16z(sb, Bm + (size_t)gnc*K + kb + col, gn < N);
        }
        asm volatile("cp.async.commit_group;\n");
    };

    load_stage(0, 0);
    for (int kt = 0; kt < nkt; ++kt){
        asm volatile("cp.async.wait_group 0;\n");
        __syncthreads();
        if (kt + 1 < nkt) load_stage((kt + 1) & 1, (kt + 1) << 5);
        const uint32_t* as = (const uint32_t*)(As + (kt & 1)*GSZ);
        const uint32_t* bs = (const uint32_t*)(Bs + (kt & 1)*GSZ);
        #pragma unroll
        for (int kk = 0; kk < 32; kk += 8){
            uint32_t af[4][4], bf[4][2];
            #pragma unroll
            for (int ma=0; ma<4; ma++){
                int row = wm + ma*16 + (lane>>2);
                int col = kk + (lane&3);
                af[ma][0] = as[row*36 + col];
                af[ma][1] = as[(row+8)*36 + col];
                af[ma][2] = as[row*36 + col + 4];
                af[ma][3] = as[(row+8)*36 + col + 4];
            }
            #pragma unroll
            for (int na=0; na<4; na++){
                int row = wn + na*8 + (lane>>2);
                int col = kk + (lane&3);
                bf[na][0] = bs[row*36 + col];
                bf[na][1] = bs[row*36 + col + 4];
            }
            #pragma unroll
            for (int ma=0; ma<4; ma++)
                #pragma unroll
                for (int na=0; na<4; na++){
                    asm volatile(
                      "mma.sync.aligned.m16n8k8.row.col.f32.tf32.tf32.f32 "
                      "{%0,%1,%2,%3}, {%4,%5,%6,%7}, {%8,%9}, {%0,%1,%2,%3};\n"
                      : "+f"(acc[ma][na][0]), "+f"(acc[ma][na][1]),
                        "+f"(acc[ma][na][2]), "+f"(acc[ma][na][3])
                      : "r"(af[ma][0]), "r"(af[ma][1]), "r"(af[ma][2]), "r"(af[ma][3]),
                        "r"(bf[na][0]), "r"(bf[na][1]));
                }
        }
    }
    // epilogue: c0->(r,c) c1->(r,c+1) c2->(r+8,c) c3->(r+8,c+1)
    #pragma unroll
    for (int ma=0; ma<4; ma++){
        int row = bm + wm + ma*16 + (lane>>2);
        #pragma unroll
        for (int na=0; na<4; na++){
            int col = bn + wn + na*8 + (lane&3)*2;
            #pragma unroll
            for (int q=0;q<4;q++){
                int rr = row + ((q>=2) ? 8 : 0);
                int cc = col + (q&1);
                if (cc < N){
                    float x = acc[ma][na][q] + bias1[cc];
                    if (bias2) x += bias2[cc];
                    if (act==1)      x = 1.f/(1.f+__expf(-x));
                    else if (act==2) x = tanhf(x);
                    C[(size_t)rr*N + cc] = x;
                }
            }
        }
    }
}

// ---------------- persistent LSTM scan (FFMA2 inner product) ----------------
// 128 blocks = 8 batch-groups x 16 h-slices, 128 threads each.
__global__ __launch_bounds__(128)
void atkt_lstm_kernel(const float* __restrict__ Whh){
    float* Wsh = dynsmem;                 // [4][16][256] = 64KB
    float* hsh = dynsmem + 4*16*256;      // [8][256]    = 8KB
    const int tid = threadIdx.x;
    const int bg  = blockIdx.x >> 4;        // 0..7  batch group
    const int hs  = blockIdx.x & 15;        // 0..15 h slice
    const int bl  = tid & 7;                // local batch
    const int jl  = tid >> 3;               // local h dim 0..15
    const int b   = bg*8 + bl;
    const int j   = hs*16 + jl;

    for (int idx = tid; idx < 4*16*256; idx += 128){
        int gate = idx >> 12;
        int jj   = (idx >> 8) & 15;
        int k    = idx & 255;
        Wsh[idx] = Whh[((gate<<8) + (hs<<4) + jj)*256 + k];
    }
    float c = 0.f;
    for (int t = 0; t < TT; ++t){
        __syncthreads();   // gates on tid0's barrier spin from previous step
        {
            const float4* hsrc = (const float4*)&g_hbuf[t & 1][bg*8][0]; // 512 f4
            #pragma unroll
            for (int i = 0; i < 4; ++i){
                int idx = tid + i*128;
                ((float4*)hsh)[idx] = __ldcg(hsrc + idx);
            }
        }
        __syncthreads();
        const int bt = b*TT + t;
        const float* xr = g_xg + (size_t)bt*G4;
        u64 ai2 = pack1(xr[j]);
        u64 af2 = pack1(xr[256+j]);
        u64 ag2 = pack1(xr[512+j]);
        u64 ao2 = pack1(xr[768+j]);
        const ulonglong2* hv = (const ulonglong2*)&hsh[bl*256];
        const ulonglong2* wi = (const ulonglong2*)&Wsh[(0*16 + jl)*256];
        const ulonglong2* wf = (const ulonglong2*)&Wsh[(1*16 + jl)*256];
        const ulonglong2* wg = (const ulonglong2*)&Wsh[(2*16 + jl)*256];
        const ulonglong2* wo = (const ulonglong2*)&Wsh[(3*16 + jl)*256];
        #pragma unroll 8
        for (int k4 = 0; k4 < 64; ++k4){
            ulonglong2 h2 = hv[k4];
            ulonglong2 w;
            w = wi[k4]; ffma2(ai2, h2.x, w.x); ffma2(ai2, h2.y, w.y);
            w = wf[k4]; ffma2(af2, h2.x, w.x); ffma2(af2, h2.y, w.y);
            w = wg[k4]; ffma2(ag2, h2.x, w.x); ffma2(ag2, h2.y, w.y);
            w = wo[k4]; ffma2(ao2, h2.x, w.x); ffma2(ao2, h2.y, w.y);
        }
        float ai = hsum2(ai2), af = hsum2(af2), ag = hsum2(ag2), ao = hsum2(ao2);
        c = sigf(af)*c + sigf(ai)*tanhf(ag);
        float h = sigf(ao)*tanhf(c);
        g_hall[(size_t)bt*HH + j] = rnd_tf(h);   // GEMM/attn operand: pre-rounded
        __stcg(&g_hbuf[(t+1)&1][b][j], h);       // recurrence: full precision
        __syncthreads();
        if (tid == 0){
            __threadfence();                     // publish (CTA-cumulative) at gpu scope
            atomicAdd(&g_cnt[bg], 1);
            int tgt = 16*(t+1);
            int v;
            do {
                asm volatile("ld.global.acquire.gpu.s32 %0, [%1];"
                             : "=r"(v) : "l"(&g_cnt[bg]) : "memory");
            } while (v < tgt);
        }
    }
}

// ---------------- scores = P(32768x80) . sim_w ----------------
__global__ void atkt_score_reduce(const float* __restrict__ sim_w){
    int r = blockIdx.x*8 + (threadIdx.x >> 5);
    int lane = threadIdx.x & 31;
    float p = 0.f;
    for (int a = lane; a < ATTD; a += 32)
        p += g_P[(size_t)r*ATTD + a] * sim_w[a];
    #pragma unroll
    for (int o = 16; o; o >>= 1) p += __shfl_xor_sync(0xffffffffu, p, o);
    if (lane == 0) g_scores[r] = p;
}

// ---------------- causal attention + exclusive cumsum -> final=[cum1|h] -----
// 128 blocks = 64 batches x 2 halves of the H dim, 128 threads each.
__global__ void atkt_attn_kernel(){
    const int b   = blockIdx.x >> 1;
    const int j   = ((blockIdx.x & 1) << 7) + threadIdx.x;
    const int tid = threadIdx.x;           // 128
    __shared__ float e_sh[TT];
    __shared__ float red[128];
    float m = -1e30f;
    for (int t = tid; t < TT; t += 128) m = fmaxf(m, g_scores[b*TT + t]);
    red[tid] = m; __syncthreads();
    for (int s = 64; s; s >>= 1){
        if (tid < s) red[tid] = fmaxf(red[tid], red[tid+s]);
        __syncthreads();
    }
    float mm = red[0];
    for (int t = tid; t < TT; t += 128) e_sh[t] = __expf(g_scores[b*TT + t] - mm);
    __syncthreads();
    float num = 0.f, den = 0.f, acc2 = 0.f;
    for (int t = 0; t < TT; ++t){
        float hv = g_hall[((size_t)b*TT + t)*HH + j];  // already tf32-rounded
        float ev = e_sh[t];
        den += ev; num += ev*hv;
        float attn = num/den;
        size_t o = ((size_t)b*TT + t)*(2*HH);
        g_final[o + j]      = rnd_tf(acc2);  // exclusive cumsum, pre-rounded
        g_final[o + HH + j] = hv;
        acc2 += attn;
    }
}

// ---------------- host launch ----------------
extern "C" void kernel_launch(void* const* d_in, const int* in_sizes, int n_in,
                              void* d_out, int out_size){
    const int*   skill      = (const int*)  d_in[0];
    const int*   answer     = (const int*)  d_in[1];
    const float* skill_emb  = (const float*)d_in[2];
    const float* answer_emb = (const float*)d_in[3];
    const float* Wih        = (const float*)d_in[4];
    const float* Whh        = (const float*)d_in[5];
    const float* bih        = (const float*)d_in[6];
    const float* bhh        = (const float*)d_in[7];
    const float* mlp_w      = (const float*)d_in[8];
    const float* mlp_b      = (const float*)d_in[9];
    const float* sim_w      = (const float*)d_in[10];
    const float* fc_w       = (const float*)d_in[11];
    const float* fc_b       = (const float*)d_in[12];
    float* out = (float*)d_out;

    float *p_sae, *p_xg, *p_hall, *p_P, *p_final, *p_wih, *p_mlpw, *p_fcw;
    cudaGetSymbolAddress((void**)&p_sae,   g_sae);
    cudaGetSymbolAddress((void**)&p_xg,    g_xg);
    cudaGetSymbolAddress((void**)&p_hall,  g_hall);
    cudaGetSymbolAddress((void**)&p_P,     g_P);
    cudaGetSymbolAddress((void**)&p_final, g_final);
    cudaGetSymbolAddress((void**)&p_wih,   g_wih_r);
    cudaGetSymbolAddress((void**)&p_mlpw,  g_mlpw_r);
    cudaGetSymbolAddress((void**)&p_fcw,   g_fcw_r);

    cudaFuncSetAttribute(atkt_lstm_kernel,
                         cudaFuncAttributeMaxDynamicSharedMemorySize, 73728);
    cudaFuncSetAttribute(atkt_gemm_tf32,
                         cudaFuncAttributeMaxDynamicSharedMemorySize, 73728);

    float* out_sae = ((size_t)out_size >= RES_ELEMS + SAE_ELEMS)
                     ? (out + RES_ELEMS) : nullptr;

    // 0) pre-round weights to tf32 (rna) once per call
    atkt_round_tf32<<<(G4*DD + 255)/256, 256>>>(Wih, p_wih, G4*DD);
    atkt_round_tf32<<<(ATTD*HH + 255)/256, 256>>>(mlp_w, p_mlpw, ATTD*HH);
    atkt_round_tf32<<<(NC*2*HH + 255)/256, 256>>>(fc_w, p_fcw, NC*2*HH);
    // 1) reset barrier counters + h0
    atkt_reset_kernel<<<(2*BB*HH + 1023)/1024, 1024>>>();
    // 2) embeddings -> sae (rounded) + exact tail of output
    atkt_embed_kernel<<<BT, DD>>>(skill, answer, skill_emb, answer_emb, out_sae);
    // 3) xg = sae @ Wih^T + bih + bhh   [32768 x 1024]
    atkt_gemm_tf32<<<dim3(G4/128, BT/128), 256, 73728>>>(
        p_sae, p_wih, bih, bhh, p_xg, BT, G4, DD, 0);
    // 4) LSTM scan -> g_hall (rounded)
    atkt_lstm_kernel<<<128, 128, 73728>>>(Whh);
    // 5) P = tanh(h @ mlp_w^T + mlp_b)  [32768 x 80]
    atkt_gemm_tf32<<<dim3(1, BT/128), 256, 73728>>>(
        p_hall, p_mlpw, mlp_b, nullptr, p_P, BT, ATTD, HH, 2);
    // 6) scores = P . sim_w
    atkt_score_reduce<<<BT/8, 256>>>(sim_w);
    // 7) causal attention cumulative ratios -> final = [cum1 | h]
    atkt_attn_kernel<<<2*BB, 128>>>();
    // 8) res = sigmoid(final @ fc_w^T + fc_b)  [32768 x 2000] -> d_out
    atkt_gemm_tf32<<<dim3((NC + 127)/128, BT/128), 256, 73728>>>(
        p_final, p_fcw, fc_b, nullptr, out, BT, NC, 2*HH, 1);
}

// round 7
// speedup vs baseline: 1.1173x; 1.0850x over previous
#include <cuda_runtime.h>
#include <cuda_fp16.h>
#include <cstdint>

// ---------------- problem constants ----------------
#define BB   64
#define TT   512
#define BT   (BB*TT)          // 32768
#define SKD  256
#define AND_ 96
#define DD   352              // SK+AN
#define HH   256
#define G4   1024             // 4*H
#define ATTD 80
#define NC   2000
#define RES_ELEMS ((size_t)BT*NC)    // 65,536,000
#define SAE_ELEMS ((size_t)BT*DD)    // 11,534,336

typedef unsigned long long u64;

// ---------------- device scratch (static, allowed) ----------------
__device__ __half g_sae_h  [BT*DD];        // 23 MB  (fp16 GEMM A)
__device__ float  g_xg     [BT*G4];        // 134 MB (fp32)
__device__ __half g_hall_h [BT*HH];        // 16.8 MB
__device__ float  g_P      [BT*ATTD];      // 10.5 MB
__device__ float  g_scores [BT];
__device__ __half g_final_h[BT*2*HH];      // 33.5 MB
__device__ float  g_hbuf [2][BB][HH];      // ping-pong h state (full fp32)
__device__ int    g_cnt  [8];              // per batch-group barrier counters
// fp16 weight copies
__device__ __half g_wih_h [G4*DD];
__device__ __half g_mlpw_h[ATTD*HH];
__device__ __half g_fcw_h [NC*2*HH];

extern __shared__ float dynsmem[];

// ---------------- helpers ----------------
__device__ __forceinline__ float sigf(float x){ return 1.f/(1.f+__expf(-x)); }
__device__ __forceinline__ void ffma2(u64& d, u64 a, u64 b){
    asm volatile("fma.rn.f32x2 %0, %1, %2, %0;" : "+l"(d) : "l"(a), "l"(b));
}
__device__ __forceinline__ u64 pack1(float x){
    float2 f = make_float2(x, 0.f); return *reinterpret_cast<u64*>(&f);
}
__device__ __forceinline__ float hsum2(u64 v){
    float2 f = *reinterpret_cast<float2*>(&v); return f.x + f.y;
}
__device__ __forceinline__ void cpa16(uint32_t s, const void* g){
    asm volatile("cp.async.cg.shared.global [%0], [%1], 16;\n" :: "r"(s), "l"(g));
}
__device__ __forceinline__ void cpa16z(uint32_t s, const void* g, int ok){
    int bytes = ok ? 16 : 0;
    asm volatile("cp.async.cg.shared.global [%0], [%1], 16, %2;\n"
                 :: "r"(s), "l"(g), "r"(bytes));
}
__device__ __forceinline__ uint32_t smem_u32(const void* p){
    uint32_t a;
    asm("{ .reg .u64 t; cvta.to.shared.u64 t, %1; cvt.u32.u64 %0, t; }"
        : "=r"(a) : "l"(p));
    return a;
}

// ---------------- float -> half convert ----------------
__global__ void atkt_f2h(const float* __restrict__ src,
                         __half* __restrict__ dst, int n){
    int i = blockIdx.x*blockDim.x + threadIdx.x;
    if (i < n) dst[i] = __float2half_rn(src[i]);
}

// ---------------- reset: counters + h0 = 0 ----------------
__global__ void atkt_reset_kernel(){
    int idx = blockIdx.x*blockDim.x + threadIdx.x;
    if (idx < 2*BB*HH) ((float*)g_hbuf)[idx] = 0.f;
    if (idx < 8) g_cnt[idx] = 0;
}

// ---------------- embedding gather + concat ----------------
__global__ void atkt_embed_kernel(const int* __restrict__ skill,
                                  const int* __restrict__ answer,
                                  const float* __restrict__ skill_emb,
                                  const float* __restrict__ answer_emb,
                                  float* __restrict__ out_sae){
    int bt = blockIdx.x;
    int d  = threadIdx.x;            // 0..351
    int ans = answer[bt];
    int sk  = skill[bt];
    float v;
    if (ans == 1) v = (d < SKD) ? skill_emb[sk*SKD + d]
                                : answer_emb[ans*AND_ + (d - SKD)];
    else          v = (d < AND_) ? answer_emb[ans*AND_ + d]
                                 : skill_emb[sk*SKD + (d - AND_)];
    size_t idx = (size_t)bt*DD + d;
    g_sae_h[idx] = __float2half_rn(v);   // GEMM operand
    if (out_sae) out_sae[idx] = v;       // exact output tail
}

// ================= fp16 mma GEMM =================
// C(MxN) = act(A(MxK) * B(NxK)^T + bias1 [+bias2]); A,B fp16, accum f32.
// block tile 128x128, K-tile 32, 3-stage cp.async ring, 8 warps (2Mx4N),
// warp tile 64x32, mma m16n8k16. M%128==0, K%32==0. act:0=none,1=sig,2=tanh
// Stage layout (halves): [A: 128 rows x 40 (cols 0..31 data)] then
//                        [B: 128 rows x 40] => HSTG = 10240 halves/stage.
#define HSTG 10240
__global__ __launch_bounds__(256, 2)
void atkt_gemm_h(const __half* __restrict__ A, const __half* __restrict__ Bm,
                 const float* __restrict__ bias1, const float* __restrict__ bias2,
                 float* __restrict__ C, int M, int N, int K, int act){
    __half* smh = (__half*)dynsmem;          // [3][HSTG] halves
    const int tid  = threadIdx.x;
    const int lane = tid & 31, warp = tid >> 5;
    const int bm = blockIdx.y * 128, bn = blockIdx.x * 128;
    const int wm = (warp & 1) * 64, wn = (warp >> 1) * 32;
    const uint32_t sm0 = smem_u32(smh);

    float acc[4][4][4];
    #pragma unroll
    for (int i=0;i<4;i++)
      #pragma unroll
      for (int j=0;j<4;j++)
        #pragma unroll
        for (int q=0;q<4;q++) acc[i][j][q]=0.f;

    const int nkt = K >> 5;

    // stage loader: per array 512 x 16B chunks, 2 per thread
    // byte offsets: stage s at s*HSTG*2 bytes; B at +HSTG bytes within stage
    auto load_stage = [&](int s, int kt){
        int kb = kt << 5;
        #pragma unroll
        for (int i = 0; i < 2; ++i){
            int idx = tid + (i << 8);        // 0..511
            int row = idx >> 2;
            int c8  = (idx & 3) << 3;        // half col 0,8,16,24
            uint32_t so = sm0 + (uint32_t)s*(HSTG*2) + row*80 + (c8<<1);
            cpa16(so, A + (size_t)(bm + row)*K + kb + c8);
            int gn = bn + row;
            int gnc = (gn < N) ? gn : (N - 1);
            cpa16z(so + (HSTG), Bm + (size_t)gnc*K + kb + c8, gn < N);
        }
        asm volatile("cp.async.commit_group;\n");
    };

    load_stage(0, 0);
    if (nkt > 1) load_stage(1, 1);
    for (int kt = 0; kt < nkt; ++kt){
        if (kt == nkt - 1) asm volatile("cp.async.wait_group 0;\n");
        else               asm volatile("cp.async.wait_group 1;\n");
        __syncthreads();
        if (kt + 2 < nkt) load_stage((kt + 2) % 3, kt + 2);
        const int s = kt % 3;
        // FIX: pointer math in HALF units to match loader byte offsets.
        // stage base = smh + s*HSTG halves; B array at +5120 halves (=2560 u32)
        const uint32_t* a32 = (const uint32_t*)(smh + (size_t)s*HSTG);
        const uint32_t* b32 = a32 + 2560;
        #pragma unroll
        for (int ks = 0; ks < 2; ++ks){
            const int kk2 = ks << 3;               // uint32 col offset (0|8)
            uint32_t af[4][4], bf[4][2];
            #pragma unroll
            for (int ma=0; ma<4; ma++){
                int r = wm + ma*16 + (lane>>2);
                int base = r*20 + kk2 + (lane&3);
                af[ma][0] = a32[base];
                af[ma][1] = a32[base + 8*20];
                af[ma][2] = a32[base + 4];
                af[ma][3] = a32[base + 8*20 + 4];
            }
            #pragma unroll
            for (int na=0; na<4; na++){
                int r = wn + na*8 + (lane>>2);
                int base = r*20 + kk2 + (lane&3);
                bf[na][0] = b32[base];
                bf[na][1] = b32[base + 4];
            }
            #pragma unroll
            for (int ma=0; ma<4; ma++)
                #pragma unroll
                for (int na=0; na<4; na++){
                    asm volatile(
                      "mma.sync.aligned.m16n8k16.row.col.f32.f16.f16.f32 "
                      "{%0,%1,%2,%3}, {%4,%5,%6,%7}, {%8,%9}, {%0,%1,%2,%3};\n"
                      : "+f"(acc[ma][na][0]), "+f"(acc[ma][na][1]),
                        "+f"(acc[ma][na][2]), "+f"(acc[ma][na][3])
                      : "r"(af[ma][0]), "r"(af[ma][1]), "r"(af[ma][2]), "r"(af[ma][3]),
                        "r"(bf[na][0]), "r"(bf[na][1]));
                }
        }
    }
    // epilogue: c0->(r,c) c1->(r,c+1) c2->(r+8,c) c3->(r+8,c+1)
    #pragma unroll
    for (int ma=0; ma<4; ma++){
        int row = bm + wm + ma*16 + (lane>>2);
        #pragma unroll
        for (int na=0; na<4; na++){
            int col = bn + wn + na*8 + (lane&3)*2;
            #pragma unroll
            for (int q=0;q<4;q++){
                int rr = row + ((q>=2) ? 8 : 0);
                int cc = col + (q&1);
                if (cc < N){
                    float x = acc[ma][na][q] + bias1[cc];
                    if (bias2) x += bias2[cc];
                    if (act==1)      x = sigf(x);
                    else if (act==2) x = tanhf(x);
                    C[(size_t)rr*N + cc] = x;
                }
            }
        }
    }
}
#define GEMM_SMEM (3*HSTG*2)   // 61440 bytes

// ---------------- persistent LSTM scan (FFMA2 + xr prefetch) ----------------
// 128 blocks = 8 batch-groups x 16 h-slices, 128 threads each.
__global__ __launch_bounds__(128)
void atkt_lstm_kernel(const float* __restrict__ Whh){
    float* Wsh = dynsmem;                 // [4][16][256] = 64KB
    float* hsh = dynsmem + 4*16*256;      // [8][256]
    const int tid = threadIdx.x;
    const int bg  = blockIdx.x >> 4;
    const int hs  = blockIdx.x & 15;
    const int bl  = tid & 7;
    const int jl  = tid >> 3;
    const int b   = bg*8 + bl;
    const int j   = hs*16 + jl;

    for (int idx = tid; idx < 4*16*256; idx += 128){
        int gate = idx >> 12;
        int jj   = (idx >> 8) & 15;
        int k    = idx & 255;
        Wsh[idx] = Whh[((gate<<8) + (hs<<4) + jj)*256 + k];
    }
    float c = 0.f;
    // prefetch xr for t=0
    const float* xr0 = g_xg + (size_t)(b*TT)*G4;
    float nai = xr0[j], naf = xr0[256+j], nag = xr0[512+j], nao = xr0[768+j];

    for (int t = 0; t < TT; ++t){
        __syncthreads();   // gates on tid0's barrier spin from previous step
        {
            const float4* hsrc = (const float4*)&g_hbuf[t & 1][bg*8][0];
            #pragma unroll
            for (int i = 0; i < 4; ++i){
                int idx = tid + i*128;
                ((float4*)hsh)[idx] = __ldcg(hsrc + idx);
            }
        }
        __syncthreads();
        u64 ai2 = pack1(nai);
        u64 af2 = pack1(naf);
        u64 ag2 = pack1(nag);
        u64 ao2 = pack1(nao);
        const ulonglong2* hv = (const ulonglong2*)&hsh[bl*256];
        const ulonglong2* wi = (const ulonglong2*)&Wsh[(0*16 + jl)*256];
        const ulonglong2* wf = (const ulonglong2*)&Wsh[(1*16 + jl)*256];
        const ulonglong2* wg = (const ulonglong2*)&Wsh[(2*16 + jl)*256];
        const ulonglong2* wo = (const ulonglong2*)&Wsh[(3*16 + jl)*256];
        #pragma unroll 8
        for (int k4 = 0; k4 < 64; ++k4){
            ulonglong2 h2 = hv[k4];
            ulonglong2 w;
            w = wi[k4]; ffma2(ai2, h2.x, w.x); ffma2(ai2, h2.y, w.y);
            w = wf[k4]; ffma2(af2, h2.x, w.x); ffma2(af2, h2.y, w.y);
            w = wg[k4]; ffma2(ag2, h2.x, w.x); ffma2(ag2, h2.y, w.y);
            w = wo[k4]; ffma2(ao2, h2.x, w.x); ffma2(ao2, h2.y, w.y);
        }
        float ai = hsum2(ai2), af = hsum2(af2), ag = hsum2(ag2), ao = hsum2(ao2);
        c = sigf(af)*c + sigf(ai)*tanhf(ag);
        float h = sigf(ao)*tanhf(c);
        const int bt = b*TT + t;
        g_hall_h[(size_t)bt*HH + j] = __float2half_rn(h);
        __stcg(&g_hbuf[(t+1)&1][b][j], h);
        // prefetch xr for t+1 (overlaps with barrier spin below)
        if (t + 1 < TT){
            const float* xr = g_xg + (size_t)(bt + 1)*G4;
            nai = __ldcg(xr + j);
            naf = __ldcg(xr + 256 + j);
            nag = __ldcg(xr + 512 + j);
            nao = __ldcg(xr + 768 + j);
        }
        __syncthreads();
        if (tid == 0){
            __threadfence();
            atomicAdd(&g_cnt[bg], 1);
            int tgt = 16*(t+1);
            int v;
            do {
                asm volatile("ld.global.acquire.gpu.s32 %0, [%1];"
                             : "=r"(v) : "l"(&g_cnt[bg]) : "memory");
            } while (v < tgt);
        }
    }
}

// ---------------- scores = P(32768x80) . sim_w ----------------
__global__ void atkt_score_reduce(const float* __restrict__ sim_w){
    int r = blockIdx.x*8 + (threadIdx.x >> 5);
    int lane = threadIdx.x & 31;
    float p = 0.f;
    for (int a = lane; a < ATTD; a += 32)
        p += g_P[(size_t)r*ATTD + a] * sim_w[a];
    #pragma unroll
    for (int o = 16; o; o >>= 1) p += __shfl_xor_sync(0xffffffffu, p, o);
    if (lane == 0) g_scores[r] = p;
}

// ---------------- causal attention + exclusive cumsum -> final=[cum1|h] -----
// 128 blocks = 64 batches x 2 halves of the H dim.
__global__ void atkt_attn_kernel(){
    const int b   = blockIdx.x >> 1;
    const int j   = ((blockIdx.x & 1) << 7) + threadIdx.x;
    const int tid = threadIdx.x;
    __shared__ float e_sh[TT];
    __shared__ float red[128];
    float m = -1e30f;
    for (int t = tid; t < TT; t += 128) m = fmaxf(m, g_scores[b*TT + t]);
    red[tid] = m; __syncthreads();
    for (int s = 64; s; s >>= 1){
        if (tid < s) red[tid] = fmaxf(red[tid], red[tid+s]);
        __syncthreads();
    }
    float mm = red[0];
    for (int t = tid; t < TT; t += 128) e_sh[t] = __expf(g_scores[b*TT + t] - mm);
    __syncthreads();
    float num = 0.f, den = 0.f, acc2 = 0.f;
    for (int t = 0; t < TT; ++t){
        __half hvh = g_hall_h[((size_t)b*TT + t)*HH + j];
        float hv = __half2float(hvh);
        float ev = e_sh[t];
        den += ev; num += ev*hv;
        float attn = num/den;
        size_t o = ((size_t)b*TT + t)*(2*HH);
        g_final_h[o + j]      = __float2half_rn(acc2);
        g_final_h[o + HH + j] = hvh;
        acc2 += attn;
    }
}

// ---------------- host launch ----------------
extern "C" void kernel_launch(void* const* d_in, const int* in_sizes, int n_in,
                              void* d_out, int out_size){
    const int*   skill      = (const int*)  d_in[0];
    const int*   answer     = (const int*)  d_in[1];
    const float* skill_emb  = (const float*)d_in[2];
    const float* answer_emb = (const float*)d_in[3];
    const float* Wih        = (const float*)d_in[4];
    const float* Whh        = (const float*)d_in[5];
    const float* bih        = (const float*)d_in[6];
    const float* bhh        = (const float*)d_in[7];
    const float* mlp_w      = (const float*)d_in[8];
    const float* mlp_b      = (const float*)d_in[9];
    const float* sim_w      = (const float*)d_in[10];
    const float* fc_w       = (const float*)d_in[11];
    const float* fc_b       = (const float*)d_in[12];
    float* out = (float*)d_out;

    __half *p_saeh, *p_hallh, *p_finalh, *p_wihh, *p_mlpwh, *p_fcwh;
    float  *p_xg, *p_P;
    cudaGetSymbolAddress((void**)&p_saeh,   g_sae_h);
    cudaGetSymbolAddress((void**)&p_xg,     g_xg);
    cudaGetSymbolAddress((void**)&p_hallh,  g_hall_h);
    cudaGetSymbolAddress((void**)&p_P,      g_P);
    cudaGetSymbolAddress((void**)&p_finalh, g_final_h);
    cudaGetSymbolAddress((void**)&p_wihh,   g_wih_h);
    cudaGetSymbolAddress((void**)&p_mlpwh,  g_mlpw_h);
    cudaGetSymbolAddress((void**)&p_fcwh,   g_fcw_h);

    cudaFuncSetAttribute(atkt_lstm_kernel,
                         cudaFuncAttributeMaxDynamicSharedMemorySize, 73728);
    cudaFuncSetAttribute(atkt_gemm_h,
                         cudaFuncAttributeMaxDynamicSharedMemorySize, GEMM_SMEM);

    float* out_sae = ((size_t)out_size >= RES_ELEMS + SAE_ELEMS)
                     ? (out + RES_ELEMS) : nullptr;

    // 0) weights -> fp16
    atkt_f2h<<<(G4*DD + 255)/256, 256>>>(Wih, p_wihh, G4*DD);
    atkt_f2h<<<(ATTD*HH + 255)/256, 256>>>(mlp_w, p_mlpwh, ATTD*HH);
    atkt_f2h<<<(NC*2*HH + 255)/256, 256>>>(fc_w, p_fcwh, NC*2*HH);
    // 1) reset barrier counters + h0
    atkt_reset_kernel<<<(2*BB*HH + 1023)/1024, 1024>>>();
    // 2) embeddings -> sae_h + exact tail of output
    atkt_embed_kernel<<<BT, DD>>>(skill, answer, skill_emb, answer_emb, out_sae);
    // 3) xg = sae @ Wih^T + bih + bhh   [32768 x 1024]
    atkt_gemm_h<<<dim3(G4/128, BT/128), 256, GEMM_SMEM>>>(
        p_saeh, p_wihh, bih, bhh, p_xg, BT, G4, DD, 0);
    // 4) LSTM scan -> g_hall_h
    atkt_lstm_kernel<<<128, 128, 73728>>>(Whh);
    // 5) P = tanh(h @ mlp_w^T + mlp_b)  [32768 x 80]
    atkt_gemm_h<<<dim3(1, BT/128), 256, GEMM_SMEM>>>(
        p_hallh, p_mlpwh, mlp_b, nullptr, p_P, BT, ATTD, HH, 2);
    // 6) scores = P . sim_w
    atkt_score_reduce<<<BT/8, 256>>>(sim_w);
    // 7) causal attention cumulative ratios -> final = [cum1 | h]
    atkt_attn_kernel<<<2*BB, 128>>>();
    // 8) res = sigmoid(final @ fc_w^T + fc_b)  [32768 x 2000] -> d_out
    atkt_gemm_h<<<dim3((NC + 127)/128, BT/128), 256, GEMM_SMEM>>>(
        p_finalh, p_fcwh, fc_b, nullptr, out, BT, NC, 2*HH, 1);
}